// round 1
// baseline (speedup 1.0000x reference)
#include <cuda_runtime.h>

#define BATCH 4
#define H 1024
#define W 1024
#define IMG (H * W)
#define NPIX (BATCH * IMG)

// ---------------- scratch (static __device__, no allocation) ----------------
__device__ float        g_bufA[NPIX];   // gray -> blurV output
__device__ float        g_bufB[NPIX];   // blurH output -> magnitude
__device__ unsigned char g_dir[NPIX];   // quantized gradient direction 0..7
__device__ unsigned char g_state[NPIX]; // 0=none, 1=weak, 2=strong
__device__ unsigned int g_parent[NPIX]; // union-find parent
__device__ unsigned char g_flag[NPIX];  // root-has-strong flag

// neighbor offsets, kornia direction order: 0 = right, clockwise
__constant__ int c_dy[8] = { 0, 1, 1, 1, 0, -1, -1, -1 };
__constant__ int c_dx[8] = { 1, 1, 0, -1, -1, -1, 0, 1 };

// Gaussian 5-tap, sigma=1 (normalized, f32)
#define GW0 0.40261994f
#define GW1 0.24420134f
#define GW2 0.05448868f

// ---------------- stage kernels ----------------

__global__ void k_gray(const float* __restrict__ x) {
    int px = blockIdx.x * blockDim.x + threadIdx.x;
    int py = blockIdx.y * blockDim.y + threadIdx.y;
    int b  = blockIdx.z;
    int o  = py * W + px;
    const float* base = x + (size_t)b * 3 * IMG;
    float r  = base[o];
    float g  = base[IMG + o];
    float bl = base[2 * IMG + o];
    g_bufA[b * IMG + o] = 0.299f * r + 0.587f * g + 0.114f * bl;
}

__device__ __forceinline__ int reflect_idx(int i, int n) {
    if (i < 0) return -i;
    if (i >= n) return 2 * n - 2 - i;
    return i;
}

__global__ void k_blurH() {
    int px = blockIdx.x * blockDim.x + threadIdx.x;
    int py = blockIdx.y * blockDim.y + threadIdx.y;
    int b  = blockIdx.z;
    const float* in = g_bufA + (size_t)b * IMG + (size_t)py * W;
    float s = 0.f;
    const float w[5] = { GW2, GW1, GW0, GW1, GW2 };
#pragma unroll
    for (int k = 0; k < 5; k++) {
        int xx = reflect_idx(px + k - 2, W);
        s += w[k] * in[xx];
    }
    g_bufB[(size_t)b * IMG + py * W + px] = s;
}

__global__ void k_blurV() {
    int px = blockIdx.x * blockDim.x + threadIdx.x;
    int py = blockIdx.y * blockDim.y + threadIdx.y;
    int b  = blockIdx.z;
    const float* in = g_bufB + (size_t)b * IMG;
    float s = 0.f;
    const float w[5] = { GW2, GW1, GW0, GW1, GW2 };
#pragma unroll
    for (int k = 0; k < 5; k++) {
        int yy = reflect_idx(py + k - 2, H);
        s += w[k] * in[yy * W + px];
    }
    g_bufA[(size_t)b * IMG + py * W + px] = s;
}

__global__ void k_sobel() {
    int px = blockIdx.x * blockDim.x + threadIdx.x;
    int py = blockIdx.y * blockDim.y + threadIdx.y;
    int b  = blockIdx.z;
    const float* in = g_bufA + (size_t)b * IMG;

    int xm = px > 0 ? px - 1 : 0;
    int xp = px < W - 1 ? px + 1 : W - 1;
    int ym = py > 0 ? py - 1 : 0;
    int yp = py < H - 1 ? py + 1 : H - 1;

    float a00 = in[ym * W + xm], a01 = in[ym * W + px], a02 = in[ym * W + xp];
    float a10 = in[py * W + xm],                       a12 = in[py * W + xp];
    float a20 = in[yp * W + xm], a21 = in[yp * W + px], a22 = in[yp * W + xp];

    float gx = (a02 - a00) + 2.f * (a12 - a10) + (a22 - a20);
    float gy = (a20 - a00) + 2.f * (a21 - a01) + (a22 - a02);

    float mag = sqrtf(gx * gx + gy * gy + 1e-6f);
    float ang = atan2f(gy, gx) * 57.29577951308232f; // deg
    float q   = ang / 45.0f;
    int d = (int)rintf(q);           // round half to even, matches jnp.round
    d = ((d % 8) + 8) & 7;

    int i = b * IMG + py * W + px;
    g_bufB[i] = mag;
    g_dir[i]  = (unsigned char)d;
}

__global__ void k_nms(float* __restrict__ magOut) {
    int px = blockIdx.x * blockDim.x + threadIdx.x;
    int py = blockIdx.y * blockDim.y + threadIdx.y;
    int b  = blockIdx.z;
    int i  = b * IMG + py * W + px;

    const float* mg = g_bufB + (size_t)b * IMG;
    float m = mg[py * W + px];
    int d = g_dir[i];
    int dn = (d + 4) & 7;

    // zero-padded neighbors (conv_multi uses zero padding)
    int y1 = py + c_dy[d],  x1 = px + c_dx[d];
    int y2 = py + c_dy[dn], x2 = px + c_dx[dn];
    float n1 = (y1 >= 0 && y1 < H && x1 >= 0 && x1 < W) ? mg[y1 * W + x1] : 0.f;
    float n2 = (y2 >= 0 && y2 < H && x2 >= 0 && x2 < W) ? mg[y2 * W + x2] : 0.f;

    bool keep = (m > n1) && (m > n2);  // min(m-n1, m-n2) > 0
    float mo = keep ? m : 0.f;
    magOut[i] = mo;
    g_state[i] = mo > 0.2f ? 2 : (mo > 0.1f ? 1 : 0);
}

// ---------------- union-find hysteresis ----------------

__device__ __forceinline__ unsigned ufFind(unsigned i) {
    unsigned p = __ldcg(&g_parent[i]);
    while (p != i) {
        unsigned gp = __ldcg(&g_parent[p]);
        if (gp != p) __stcg(&g_parent[i], gp); // path halving (benign race)
        i = p;
        p = gp;
    }
    return i;
}

__device__ __forceinline__ void ufUnite(unsigned a, unsigned b) {
    while (true) {
        a = ufFind(a);
        b = ufFind(b);
        if (a == b) return;
        unsigned lo = a < b ? a : b;
        unsigned hi = a < b ? b : a;
        unsigned old = atomicCAS(&g_parent[hi], hi, lo);
        if (old == hi) return;
        a = lo;
        b = old;
    }
}

__global__ void k_uf_init() {
    unsigned i = blockIdx.x * blockDim.x + threadIdx.x;
    g_parent[i] = i;
    g_flag[i] = 0;
}

__global__ void k_uf_merge() {
    unsigned i = blockIdx.x * blockDim.x + threadIdx.x;
    if (g_state[i] == 0) return;
    int r = i & (IMG - 1);
    int y = r >> 10;
    int x = r & (W - 1);
    // union with 4 already-scanned neighbors: left, up-left, up, up-right
    if (x > 0 && g_state[i - 1]) ufUnite(i, i - 1);
    if (y > 0) {
        unsigned up = i - W;
        if (x > 0 && g_state[up - 1]) ufUnite(i, up - 1);
        if (g_state[up]) ufUnite(i, up);
        if (x < W - 1 && g_state[up + 1]) ufUnite(i, up + 1);
    }
}

__global__ void k_uf_flag() {
    unsigned i = blockIdx.x * blockDim.x + threadIdx.x;
    if (g_state[i] == 2) {
        g_flag[ufFind(i)] = 1;
    }
}

__global__ void k_final(float* __restrict__ edgeOut) {
    unsigned i = blockIdx.x * blockDim.x + threadIdx.x;
    float v = 0.f;
    if (g_state[i] != 0 && g_flag[ufFind(i)]) v = 1.f;
    edgeOut[i] = v;
}

// ---------------- launch ----------------

extern "C" void kernel_launch(void* const* d_in, const int* in_sizes, int n_in,
                              void* d_out, int out_size) {
    const float* x = (const float*)d_in[0];
    float* magOut  = (float*)d_out;
    float* edgeOut = magOut + (size_t)NPIX;

    dim3 blk(32, 8, 1);
    dim3 grd(W / 32, H / 8, BATCH);

    k_gray<<<grd, blk>>>(x);
    k_blurH<<<grd, blk>>>();
    k_blurV<<<grd, blk>>>();
    k_sobel<<<grd, blk>>>();
    k_nms<<<grd, blk>>>(magOut);

    int tb = 256;
    int nb = NPIX / tb;
    k_uf_init<<<nb, tb>>>();
    k_uf_merge<<<nb, tb>>>();
    k_uf_flag<<<nb, tb>>>();
    k_final<<<nb, tb>>>(edgeOut);
}

// round 2
// speedup vs baseline: 1.4278x; 1.4278x over previous
#include <cuda_runtime.h>

#define BATCH 4
#define H 1024
#define W 1024
#define IMG (H * W)
#define NPIX (BATCH * IMG)

// ---------------- scratch (static __device__, no allocation) ----------------
__device__ unsigned char g_state[NPIX]; // 0=none, 1=weak, 2=strong
__device__ unsigned int  g_parent[NPIX];
__device__ unsigned char g_flag[NPIX];

// neighbor offsets, kornia direction order: 0 = right, clockwise
__constant__ int c_dy[8] = { 0, 1, 1, 1, 0, -1, -1, -1 };
__constant__ int c_dx[8] = { 1, 1, 0, -1, -1, -1, 0, 1 };

// Gaussian 5-tap, sigma=1 (normalized, f32)
#define GW0 0.40261994f
#define GW1 0.24420134f
#define GW2 0.05448868f

__device__ __forceinline__ int reflect_idx(int i, int n) {
    if (i < 0) return -i;
    if (i >= n) return 2 * n - 2 - i;
    return i;
}

// ================= fused stencil =================
// tile 32x16 outputs; halo 4 gray -> halo 2 blurH -> halo 2 blurV -> halo 1 mag -> out
#define TX 32
#define TY 16

__global__ __launch_bounds__(512) void k_fused(const float* __restrict__ x,
                                               float* __restrict__ magOut) {
    __shared__ float sG[24][41];          // gray:  rows [tY-4,tY+20), cols [tX-4,tX+36)
    __shared__ float sH[24][37];          // blurH: cols [tX-2,tX+34)
    __shared__ float sV[20][37];          // blurV: rows [tY-2,tY+18)
    __shared__ float sM[18][35];          // mag:   rows [tY-1,tY+17), cols [tX-1,tX+33)
    __shared__ unsigned char sD[18][35];  // dir

    const int tileX = blockIdx.x * TX;
    const int tileY = blockIdx.y * TY;
    const int b     = blockIdx.z;
    const int tid   = threadIdx.y * TX + threadIdx.x;
    const float* base = x + (size_t)b * 3 * IMG;

    // gray with reflect-extended coords (halo 4)
    for (int idx = tid; idx < 24 * 40; idx += 512) {
        int r = idx / 40, c = idx % 40;
        int yy = reflect_idx(tileY - 4 + r, H);
        int xx = reflect_idx(tileX - 4 + c, W);
        int o = yy * W + xx;
        sG[r][c] = 0.299f * base[o] + 0.587f * base[IMG + o] + 0.114f * base[2 * IMG + o];
    }
    __syncthreads();

    // blurH: 24 rows x 36 cols  (out col c -> global x = tileX-2+c)
    for (int idx = tid; idx < 24 * 36; idx += 512) {
        int r = idx / 36, c = idx % 36;
        int gx = tileX - 2 + c;
        float s = 0.f;
        const float w[5] = { GW2, GW1, GW0, GW1, GW2 };
#pragma unroll
        for (int k = 0; k < 5; k++) {
            int lx = reflect_idx(gx + k - 2, W) - (tileX - 4);
            s += w[k] * sG[r][lx];
        }
        sH[r][c] = s;
    }
    __syncthreads();

    // blurV: 20 rows x 36 cols  (out row r -> global y = tileY-2+r)
    for (int idx = tid; idx < 20 * 36; idx += 512) {
        int r = idx / 36, c = idx % 36;
        int gy = tileY - 2 + r;
        float s = 0.f;
        const float w[5] = { GW2, GW1, GW0, GW1, GW2 };
#pragma unroll
        for (int k = 0; k < 5; k++) {
            int ly = reflect_idx(gy + k - 2, H) - (tileY - 4);
            s += w[k] * sH[ly][c];
        }
        sV[r][c] = s;
    }
    __syncthreads();

    // sobel + magnitude + direction: 18 rows x 34 cols (replicate clamp to image)
    for (int idx = tid; idx < 18 * 34; idx += 512) {
        int r = idx / 34, c = idx % 34;
        int gy = tileY - 1 + r;
        int gx = tileX - 1 + c;
        int xm = max(gx - 1, 0), xp = min(gx + 1, W - 1);
        int ym = max(gy - 1, 0), yp = min(gy + 1, H - 1);
        int xc = min(max(gx, 0), W - 1), yc = min(max(gy, 0), H - 1);
        int lxm = xm - (tileX - 2), lxp = xp - (tileX - 2), lxc = xc - (tileX - 2);
        int lym = ym - (tileY - 2), lyp = yp - (tileY - 2), lyc = yc - (tileY - 2);

        float a00 = sV[lym][lxm], a01 = sV[lym][lxc], a02 = sV[lym][lxp];
        float a10 = sV[lyc][lxm],                     a12 = sV[lyc][lxp];
        float a20 = sV[lyp][lxm], a21 = sV[lyp][lxc], a22 = sV[lyp][lxp];

        float gxv = (a02 - a00) + 2.f * (a12 - a10) + (a22 - a20);
        float gyv = (a20 - a00) + 2.f * (a21 - a01) + (a22 - a02);

        float mag = sqrtf(gxv * gxv + gyv * gyv + 1e-6f);
        float ang = atan2f(gyv, gxv) * 57.29577951308232f;
        int d = (int)rintf(ang / 45.0f);
        d = ((d % 8) + 8) & 7;
        sM[r][c] = mag;
        sD[r][c] = (unsigned char)d;
    }
    __syncthreads();

    // NMS + double threshold + UF init
    {
        int lx = threadIdx.x, ly = threadIdx.y;
        int gx = tileX + lx, gy = tileY + ly;
        float m = sM[ly + 1][lx + 1];
        int d  = sD[ly + 1][lx + 1];
        int dn = (d + 4) & 7;

        int y1 = gy + c_dy[d],  x1 = gx + c_dx[d];
        int y2 = gy + c_dy[dn], x2 = gx + c_dx[dn];
        float n1 = (y1 >= 0 && y1 < H && x1 >= 0 && x1 < W)
                   ? sM[ly + 1 + c_dy[d]][lx + 1 + c_dx[d]] : 0.f;
        float n2 = (y2 >= 0 && y2 < H && x2 >= 0 && x2 < W)
                   ? sM[ly + 1 + c_dy[dn]][lx + 1 + c_dx[dn]] : 0.f;

        bool keep = (m > n1) && (m > n2);
        float mo = keep ? m : 0.f;
        unsigned i = b * IMG + gy * W + gx;
        magOut[i]   = mo;
        g_state[i]  = mo > 0.2f ? 2 : (mo > 0.1f ? 1 : 0);
        g_parent[i] = i;
        g_flag[i]   = 0;
    }
}

// ================= union-find =================

__device__ __forceinline__ unsigned lfind(unsigned* p, unsigned i) {
    volatile unsigned* vp = (volatile unsigned*)p;
    unsigned q = vp[i];
    while (q != i) {
        unsigned qq = vp[q];
        if (qq != q) vp[i] = qq;
        i = q; q = qq;
    }
    return i;
}

__device__ __forceinline__ void lunion(unsigned* p, unsigned a, unsigned b) {
    while (true) {
        a = lfind(p, a);
        b = lfind(p, b);
        if (a == b) return;
        unsigned lo = min(a, b), hi = max(a, b);
        unsigned old = atomicCAS(&p[hi], hi, lo);
        if (old == hi) return;
        a = lo; b = old;
    }
}

__device__ __forceinline__ unsigned gfind(unsigned i) {
    unsigned p = __ldcg(&g_parent[i]);
    while (p != i) {
        unsigned gp = __ldcg(&g_parent[p]);
        if (gp != p) __stcg(&g_parent[i], gp);
        i = p; p = gp;
    }
    return i;
}

__device__ __forceinline__ void gunion(unsigned a, unsigned b) {
    while (true) {
        a = gfind(a);
        b = gfind(b);
        if (a == b) return;
        unsigned lo = min(a, b), hi = max(a, b);
        unsigned old = atomicCAS(&g_parent[hi], hi, lo);
        if (old == hi) return;
        a = lo; b = old;
    }
}

// local CCL per 32x32 tile in shared memory
__global__ __launch_bounds__(1024) void k_merge_local() {
    __shared__ unsigned lp[1024];
    __shared__ unsigned char ls[1024];

    int tx = threadIdx.x, ty = threadIdx.y;
    int gx = blockIdx.x * 32 + tx;
    int gy = blockIdx.y * 32 + ty;
    int b  = blockIdx.z;
    unsigned gid = b * IMG + gy * W + gx;
    unsigned lid = ty * 32 + tx;

    ls[lid] = g_state[gid];
    lp[lid] = lid;
    __syncthreads();

    if (ls[lid]) {
        // prior neighbors within tile: left, up-left, up, up-right
        if (tx > 0            && ls[lid - 1])       lunion(lp, lid, lid - 1);
        if (ty > 0) {
            if (tx > 0        && ls[lid - 33])      lunion(lp, lid, lid - 33);
            if (ls[lid - 32])                       lunion(lp, lid, lid - 32);
            if (tx < 31       && ls[lid - 31])      lunion(lp, lid, lid - 31);
        }
    }
    __syncthreads();

    if (ls[lid]) {
        unsigned r = lfind(lp, lid);
        if (r != lid) {
            unsigned rg = b * IMG + (blockIdx.y * 32 + r / 32) * W + blockIdx.x * 32 + (r & 31);
            g_parent[gid] = rg;
        }
    }
}

// cross-tile boundary unions (global UF)
__global__ void k_merge_border() {
    unsigned i = blockIdx.x * blockDim.x + threadIdx.x;
    if (g_state[i] == 0) return;
    int r = i & (IMG - 1);
    int y = r >> 10;
    int x = r & (W - 1);

    if ((x & 31) == 0 && x > 0) {
        // unite with (x-1, y+dy)
        if (y > 0     && g_state[i - 1 - W]) gunion(i, i - 1 - W);
        if (g_state[i - 1])                  gunion(i, i - 1);
        if (y < H - 1 && g_state[i - 1 + W]) gunion(i, i - 1 + W);
    }
    if ((y & 31) == 0 && y > 0) {
        // unite with (x+dx, y-1)
        if (x > 0     && g_state[i - W - 1]) gunion(i, i - W - 1);
        if (g_state[i - W])                  gunion(i, i - W);
        if (x < W - 1 && g_state[i - W + 1]) gunion(i, i - W + 1);
    }
}

__global__ void k_flag() {
    unsigned i = blockIdx.x * blockDim.x + threadIdx.x;
    if (g_state[i] == 2) {
        unsigned root = gfind(i);
        g_parent[i] = root;   // full compression (benign)
        g_flag[root] = 1;
    }
}

__global__ void k_final(float* __restrict__ edgeOut) {
    unsigned i = blockIdx.x * blockDim.x + threadIdx.x;
    float v = 0.f;
    if (g_state[i] != 0 && g_flag[gfind(i)]) v = 1.f;
    edgeOut[i] = v;
}

// ---------------- launch ----------------

extern "C" void kernel_launch(void* const* d_in, const int* in_sizes, int n_in,
                              void* d_out, int out_size) {
    const float* x = (const float*)d_in[0];
    float* magOut  = (float*)d_out;
    float* edgeOut = magOut + (size_t)NPIX;

    dim3 fblk(TX, TY, 1);
    dim3 fgrd(W / TX, H / TY, BATCH);
    k_fused<<<fgrd, fblk>>>(x, magOut);

    dim3 mblk(32, 32, 1);
    dim3 mgrd(W / 32, H / 32, BATCH);
    k_merge_local<<<mgrd, mblk>>>();

    int tb = 256;
    int nb = NPIX / tb;
    k_merge_border<<<nb, tb>>>();
    k_flag<<<nb, tb>>>();
    k_final<<<nb, tb>>>(edgeOut);
}

// round 3
// speedup vs baseline: 1.6106x; 1.1280x over previous
#include <cuda_runtime.h>

#define BATCH 4
#define H 1024
#define W 1024
#define IMG (H * W)
#define NPIX (BATCH * IMG)

// ---------------- scratch ----------------
__device__ unsigned char g_state[NPIX]; // 0=none, 1=weak, 2=strong
__device__ unsigned int  g_parent[NPIX];
__device__ unsigned char g_flag[NPIX];
__device__ unsigned char g_lroot[NPIX]; // 1 if pixel is a tile-local root

__constant__ int c_dy[8] = { 0, 1, 1, 1, 0, -1, -1, -1 };
__constant__ int c_dx[8] = { 1, 1, 0, -1, -1, -1, 0, 1 };

#define GW0 0.40261994f
#define GW1 0.24420134f
#define GW2 0.05448868f

__device__ __forceinline__ int reflect_idx(int i, int n) {
    if (i < 0) return -i;
    if (i >= n) return 2 * n - 2 - i;
    return i;
}

// ================= fused stencil =================
#define TX 32
#define TY 16

__global__ __launch_bounds__(512) void k_fused(const float* __restrict__ x,
                                               float* __restrict__ magOut) {
    __shared__ float sG[24][41];
    __shared__ float sH[24][37];
    __shared__ float sV[20][37];
    __shared__ float sM[18][35];
    __shared__ unsigned char sD[18][35];

    const int tileX = blockIdx.x * TX;
    const int tileY = blockIdx.y * TY;
    const int b     = blockIdx.z;
    const int tid   = threadIdx.y * TX + threadIdx.x;
    const float* base = x + (size_t)b * 3 * IMG;

    for (int idx = tid; idx < 24 * 40; idx += 512) {
        int r = idx / 40, c = idx % 40;
        int yy = reflect_idx(tileY - 4 + r, H);
        int xx = reflect_idx(tileX - 4 + c, W);
        int o = yy * W + xx;
        sG[r][c] = 0.299f * base[o] + 0.587f * base[IMG + o] + 0.114f * base[2 * IMG + o];
    }
    __syncthreads();

    for (int idx = tid; idx < 24 * 36; idx += 512) {
        int r = idx / 36, c = idx % 36;
        int gx = tileX - 2 + c;
        float s = 0.f;
        const float w[5] = { GW2, GW1, GW0, GW1, GW2 };
#pragma unroll
        for (int k = 0; k < 5; k++) {
            int lx = reflect_idx(gx + k - 2, W) - (tileX - 4);
            s += w[k] * sG[r][lx];
        }
        sH[r][c] = s;
    }
    __syncthreads();

    for (int idx = tid; idx < 20 * 36; idx += 512) {
        int r = idx / 36, c = idx % 36;
        int gy = tileY - 2 + r;
        float s = 0.f;
        const float w[5] = { GW2, GW1, GW0, GW1, GW2 };
#pragma unroll
        for (int k = 0; k < 5; k++) {
            int ly = reflect_idx(gy + k - 2, H) - (tileY - 4);
            s += w[k] * sH[ly][c];
        }
        sV[r][c] = s;
    }
    __syncthreads();

    for (int idx = tid; idx < 18 * 34; idx += 512) {
        int r = idx / 34, c = idx % 34;
        int gy = tileY - 1 + r;
        int gx = tileX - 1 + c;
        int xm = max(gx - 1, 0), xp = min(gx + 1, W - 1);
        int ym = max(gy - 1, 0), yp = min(gy + 1, H - 1);
        int xc = min(max(gx, 0), W - 1), yc = min(max(gy, 0), H - 1);
        int lxm = xm - (tileX - 2), lxp = xp - (tileX - 2), lxc = xc - (tileX - 2);
        int lym = ym - (tileY - 2), lyp = yp - (tileY - 2), lyc = yc - (tileY - 2);

        float a00 = sV[lym][lxm], a01 = sV[lym][lxc], a02 = sV[lym][lxp];
        float a10 = sV[lyc][lxm],                     a12 = sV[lyc][lxp];
        float a20 = sV[lyp][lxm], a21 = sV[lyp][lxc], a22 = sV[lyp][lxp];

        float gxv = (a02 - a00) + 2.f * (a12 - a10) + (a22 - a20);
        float gyv = (a20 - a00) + 2.f * (a21 - a01) + (a22 - a02);

        float mag = sqrtf(gxv * gxv + gyv * gyv + 1e-6f);
        float ang = atan2f(gyv, gxv) * 57.29577951308232f;
        int d = (int)rintf(ang / 45.0f);
        d = ((d % 8) + 8) & 7;
        sM[r][c] = mag;
        sD[r][c] = (unsigned char)d;
    }
    __syncthreads();

    {
        int lx = threadIdx.x, ly = threadIdx.y;
        int gx = tileX + lx, gy = tileY + ly;
        float m = sM[ly + 1][lx + 1];
        int d  = sD[ly + 1][lx + 1];
        int dn = (d + 4) & 7;

        int y1 = gy + c_dy[d],  x1 = gx + c_dx[d];
        int y2 = gy + c_dy[dn], x2 = gx + c_dx[dn];
        float n1 = (y1 >= 0 && y1 < H && x1 >= 0 && x1 < W)
                   ? sM[ly + 1 + c_dy[d]][lx + 1 + c_dx[d]] : 0.f;
        float n2 = (y2 >= 0 && y2 < H && x2 >= 0 && x2 < W)
                   ? sM[ly + 1 + c_dy[dn]][lx + 1 + c_dx[dn]] : 0.f;

        bool keep = (m > n1) && (m > n2);
        float mo = keep ? m : 0.f;
        unsigned i = b * IMG + gy * W + gx;
        magOut[i]  = mo;
        g_state[i] = mo > 0.2f ? 2 : (mo > 0.1f ? 1 : 0);
    }
}

// ================= union-find =================

__device__ __forceinline__ unsigned lfind(unsigned* p, unsigned i) {
    volatile unsigned* vp = (volatile unsigned*)p;
    unsigned q = vp[i];
    while (q != i) {
        unsigned qq = vp[q];
        if (qq != q) vp[i] = qq;
        i = q; q = qq;
    }
    return i;
}

__device__ __forceinline__ void lunion(unsigned* p, unsigned a, unsigned b) {
    while (true) {
        a = lfind(p, a);
        b = lfind(p, b);
        if (a == b) return;
        unsigned lo = min(a, b), hi = max(a, b);
        unsigned old = atomicCAS(&p[hi], hi, lo);
        if (old == hi) return;
        a = lo; b = old;
    }
}

__device__ __forceinline__ unsigned gfind(unsigned i) {
    unsigned p = __ldcg(&g_parent[i]);
    while (p != i) {
        unsigned gp = __ldcg(&g_parent[p]);
        if (gp != p) __stcg(&g_parent[i], gp);
        i = p; p = gp;
    }
    return i;
}

__device__ __forceinline__ void gunion(unsigned a, unsigned b) {
    while (true) {
        a = gfind(a);
        b = gfind(b);
        if (a == b) return;
        unsigned lo = min(a, b), hi = max(a, b);
        unsigned old = atomicCAS(&g_parent[hi], hi, lo);
        if (old == hi) return;
        a = lo; b = old;
    }
}

// local CCL per 32x32 tile in shared memory; parent <- tile root, mark roots
__global__ __launch_bounds__(1024) void k_merge_local() {
    __shared__ unsigned lp[1024];
    __shared__ unsigned char ls[1024];

    int tx = threadIdx.x, ty = threadIdx.y;
    int gx = blockIdx.x * 32 + tx;
    int gy = blockIdx.y * 32 + ty;
    int b  = blockIdx.z;
    unsigned gid = b * IMG + gy * W + gx;
    unsigned lid = ty * 32 + tx;

    ls[lid] = g_state[gid];
    lp[lid] = lid;
    __syncthreads();

    if (ls[lid]) {
        if (tx > 0            && ls[lid - 1])  lunion(lp, lid, lid - 1);
        if (ty > 0) {
            if (tx > 0        && ls[lid - 33]) lunion(lp, lid, lid - 33);
            if (ls[lid - 32])                  lunion(lp, lid, lid - 32);
            if (tx < 31       && ls[lid - 31]) lunion(lp, lid, lid - 31);
        }
    }
    __syncthreads();

    if (ls[lid]) {
        unsigned r = lfind(lp, lid);
        unsigned rg = b * IMG + (blockIdx.y * 32 + (r >> 5)) * W + blockIdx.x * 32 + (r & 31);
        g_parent[gid] = rg;
        bool isroot = (r == lid);
        g_lroot[gid] = isroot ? 1 : 0;
        if (isroot) g_flag[gid] = 0;
    } else {
        g_lroot[gid] = 0;
    }
}

// cross-tile boundary unions — border pixels only, union local roots directly
#define VB_PER 31744u              // 31 * 1024
#define VB_TOT (4u * VB_PER)       // per direction

__global__ void k_merge_border() {
    unsigned id = blockIdx.x * blockDim.x + threadIdx.x;
    bool vert = id < VB_TOT;
    unsigned t = vert ? id : id - VB_TOT;
    unsigned b = t / VB_PER;
    unsigned r = t % VB_PER;

    if (vert) {
        unsigned c = r >> 10;            // 0..30
        unsigned y = r & 1023;
        unsigned x = (c + 1) << 5;       // 32..992
        unsigned i = b * IMG + y * W + x;
        if (!g_state[i]) return;
        unsigned pi = g_parent[i];
        unsigned j = i - 1;
        if (y > 0     && g_state[j - W]) gunion(pi, g_parent[j - W]);
        if (g_state[j])                  gunion(pi, g_parent[j]);
        if (y < H - 1 && g_state[j + W]) gunion(pi, g_parent[j + W]);
    } else {
        unsigned rr = r >> 10;
        unsigned x = r & 1023;
        unsigned y = (rr + 1) << 5;
        unsigned i = b * IMG + y * W + x;
        if (!g_state[i]) return;
        unsigned pi = g_parent[i];
        unsigned j = i - W;
        if (x > 0     && g_state[j - 1]) gunion(pi, g_parent[j - 1]);
        if (g_state[j])                  gunion(pi, g_parent[j]);
        if (x < W - 1 && g_state[j + 1]) gunion(pi, g_parent[j + 1]);
    }
}

// flatten: every local root points directly at its global root
__global__ void k_flatten() {
    unsigned i = blockIdx.x * blockDim.x + threadIdx.x;
    if (g_lroot[i]) {
        unsigned r = gfind(i);
        g_parent[i] = r;
    }
}

// after flatten: true root of any nonzero pixel = parent[parent[i]] (no loop)
__global__ void k_flag() {
    unsigned i = blockIdx.x * blockDim.x + threadIdx.x;
    if (g_state[i] == 2) {
        unsigned p  = __ldcg(&g_parent[i]);
        unsigned rt = __ldcg(&g_parent[p]);
        g_flag[rt] = 1;
    }
}

__global__ void k_final(float* __restrict__ edgeOut) {
    unsigned i = blockIdx.x * blockDim.x + threadIdx.x;
    float v = 0.f;
    if (g_state[i]) {
        unsigned p  = __ldcg(&g_parent[i]);
        unsigned rt = __ldcg(&g_parent[p]);
        if (g_flag[rt]) v = 1.f;
    }
    edgeOut[i] = v;
}

// ---------------- launch ----------------

extern "C" void kernel_launch(void* const* d_in, const int* in_sizes, int n_in,
                              void* d_out, int out_size) {
    const float* x = (const float*)d_in[0];
    float* magOut  = (float*)d_out;
    float* edgeOut = magOut + (size_t)NPIX;

    dim3 fblk(TX, TY, 1);
    dim3 fgrd(W / TX, H / TY, BATCH);
    k_fused<<<fgrd, fblk>>>(x, magOut);

    dim3 mblk(32, 32, 1);
    dim3 mgrd(W / 32, H / 32, BATCH);
    k_merge_local<<<mgrd, mblk>>>();

    unsigned nborder = 2u * VB_TOT;            // 253952
    k_merge_border<<<(nborder + 255) / 256, 256>>>();

    int tb = 256;
    int nb = NPIX / tb;
    k_flatten<<<nb, tb>>>();
    k_flag<<<nb, tb>>>();
    k_final<<<nb, tb>>>(edgeOut);
}

// round 4
// speedup vs baseline: 1.9815x; 1.2303x over previous
#include <cuda_runtime.h>

#define BATCH 4
#define H 1024
#define W 1024
#define IMG (H * W)
#define NPIX (BATCH * IMG)

// ---------------- scratch ----------------
__device__ unsigned char g_state[NPIX];  // 0=none, 1=weak, 2=strong
__device__ unsigned int  g_parent[NPIX];
__device__ unsigned char g_flag[NPIX];   // at local-root slots: component-has-strong
__device__ unsigned int  g_roots[NPIX];  // worklist of local roots
__device__ unsigned int  g_nroots;

__constant__ int c_dy[8] = { 0, 1, 1, 1, 0, -1, -1, -1 };
__constant__ int c_dx[8] = { 1, 1, 0, -1, -1, -1, 0, 1 };

#define GW0 0.40261994f
#define GW1 0.24420134f
#define GW2 0.05448868f

#define TAN22 0.41421356237309503f
#define TAN67 2.4142135623730951f

__device__ __forceinline__ int reflect_idx(int i, int n) {
    if (i < 0) return -i;
    if (i >= n) return 2 * n - 2 - i;
    return i;
}

__global__ void k_reset() { g_nroots = 0; }

// ---- shared-memory union-find helpers ----
__device__ __forceinline__ unsigned lfind(unsigned* p, unsigned i) {
    volatile unsigned* vp = (volatile unsigned*)p;
    unsigned q = vp[i];
    while (q != i) {
        unsigned qq = vp[q];
        if (qq != q) vp[i] = qq;
        i = q; q = qq;
    }
    return i;
}

__device__ __forceinline__ void lunion(unsigned* p, unsigned a, unsigned b) {
    while (true) {
        a = lfind(p, a);
        b = lfind(p, b);
        if (a == b) return;
        unsigned lo = min(a, b), hi = max(a, b);
        unsigned old = atomicCAS(&p[hi], hi, lo);
        if (old == hi) return;
        a = lo; b = old;
    }
}

// ---- global union-find helpers ----
__device__ __forceinline__ unsigned gfind(unsigned i) {
    unsigned p = __ldcg(&g_parent[i]);
    while (p != i) {
        unsigned gp = __ldcg(&g_parent[p]);
        if (gp != p) __stcg(&g_parent[i], gp);
        i = p; p = gp;
    }
    return i;
}

__device__ __forceinline__ void gunion(unsigned a, unsigned b) {
    while (true) {
        a = gfind(a);
        b = gfind(b);
        if (a == b) return;
        unsigned lo = min(a, b), hi = max(a, b);
        unsigned old = atomicCAS(&g_parent[hi], hi, lo);
        if (old == hi) return;
        a = lo; b = old;
    }
}

// ================= fused stencil + NMS + threshold + local CCL =================
#define TX 32
#define TY 32

__global__ __launch_bounds__(1024) void k_fused(const float* __restrict__ x,
                                                float* __restrict__ magOut) {
    __shared__ float sG[40][41];
    __shared__ float sH[40][37];
    __shared__ float sV[36][37];
    __shared__ float sM[34][35];
    __shared__ unsigned char sD[34][35];
    __shared__ unsigned      lp[1024];
    __shared__ unsigned char ls[1024];
    __shared__ unsigned char sflag[1024];
    __shared__ unsigned short slist[1024];
    __shared__ unsigned scnt, sbase;

    const int tileX = blockIdx.x * TX;
    const int tileY = blockIdx.y * TY;
    const int b     = blockIdx.z;
    const int tid   = threadIdx.y * TX + threadIdx.x;
    const float* base = x + (size_t)b * 3 * IMG;

    if (tid == 0) scnt = 0;

    // gray: 40 rows x 40 cols, reflect
    for (int idx = tid; idx < 40 * 40; idx += 1024) {
        int r = idx / 40, c = idx % 40;
        int yy = reflect_idx(tileY - 4 + r, H);
        int xx = reflect_idx(tileX - 4 + c, W);
        int o = yy * W + xx;
        sG[r][c] = 0.299f * base[o] + 0.587f * base[IMG + o] + 0.114f * base[2 * IMG + o];
    }
    __syncthreads();

    // blurH: 40 rows x 36 cols (out col c -> global x = tileX-2+c)
    for (int idx = tid; idx < 40 * 36; idx += 1024) {
        int r = idx / 36, c = idx % 36;
        int gx = tileX - 2 + c;
        float s = 0.f;
        const float w[5] = { GW2, GW1, GW0, GW1, GW2 };
#pragma unroll
        for (int k = 0; k < 5; k++) {
            int lx = reflect_idx(gx + k - 2, W) - (tileX - 4);
            s += w[k] * sG[r][lx];
        }
        sH[r][c] = s;
    }
    __syncthreads();

    // blurV: 36 rows x 36 cols (out row r -> global y = tileY-2+r)
    for (int idx = tid; idx < 36 * 36; idx += 1024) {
        int r = idx / 36, c = idx % 36;
        int gy = tileY - 2 + r;
        float s = 0.f;
        const float w[5] = { GW2, GW1, GW0, GW1, GW2 };
#pragma unroll
        for (int k = 0; k < 5; k++) {
            int ly = reflect_idx(gy + k - 2, H) - (tileY - 4);
            s += w[k] * sH[ly][c];
        }
        sV[r][c] = s;
    }
    __syncthreads();

    // sobel + magnitude + quantized direction: 34 x 34, replicate clamp
    for (int idx = tid; idx < 34 * 34; idx += 1024) {
        int r = idx / 34, c = idx % 34;
        int gy = tileY - 1 + r;
        int gx = tileX - 1 + c;
        int xm = max(gx - 1, 0), xp = min(gx + 1, W - 1);
        int ym = max(gy - 1, 0), yp = min(gy + 1, H - 1);
        int xc = min(max(gx, 0), W - 1), yc = min(max(gy, 0), H - 1);
        int lxm = xm - (tileX - 2), lxp = xp - (tileX - 2), lxc = xc - (tileX - 2);
        int lym = ym - (tileY - 2), lyp = yp - (tileY - 2), lyc = yc - (tileY - 2);

        float a00 = sV[lym][lxm], a01 = sV[lym][lxc], a02 = sV[lym][lxp];
        float a10 = sV[lyc][lxm],                     a12 = sV[lyc][lxp];
        float a20 = sV[lyp][lxm], a21 = sV[lyp][lxc], a22 = sV[lyp][lxp];

        float gxv = (a02 - a00) + 2.f * (a12 - a10) + (a22 - a20);
        float gyv = (a20 - a00) + 2.f * (a21 - a01) + (a22 - a02);

        float mag = sqrtf(gxv * gxv + gyv * gyv + 1e-6f);

        // quantized direction via tangent comparisons (== round(atan2/45) mod 8)
        float ax = fabsf(gxv), ay = fabsf(gyv);
        int d;
        if (ay <= TAN22 * ax)      d = (gxv >= 0.f) ? 0 : 4;
        else if (ay >= TAN67 * ax) d = (gyv >= 0.f) ? 2 : 6;
        else {
            if (gxv > 0.f) d = (gyv > 0.f) ? 1 : 7;
            else           d = (gyv > 0.f) ? 3 : 5;
        }
        sM[r][c] = mag;
        sD[r][c] = (unsigned char)d;
    }
    __syncthreads();

    // NMS + threshold -> state
    const int lx = threadIdx.x, ly = threadIdx.y;
    const int gx = tileX + lx, gy = tileY + ly;
    const unsigned gid = b * IMG + gy * W + gx;
    unsigned char st;
    {
        float m = sM[ly + 1][lx + 1];
        int d  = sD[ly + 1][lx + 1];
        int dn = (d + 4) & 7;

        int y1 = gy + c_dy[d],  x1 = gx + c_dx[d];
        int y2 = gy + c_dy[dn], x2 = gx + c_dx[dn];
        float n1 = (y1 >= 0 && y1 < H && x1 >= 0 && x1 < W)
                   ? sM[ly + 1 + c_dy[d]][lx + 1 + c_dx[d]] : 0.f;
        float n2 = (y2 >= 0 && y2 < H && x2 >= 0 && x2 < W)
                   ? sM[ly + 1 + c_dy[dn]][lx + 1 + c_dx[dn]] : 0.f;

        bool keep = (m > n1) && (m > n2);
        float mo = keep ? m : 0.f;
        magOut[gid] = mo;
        st = mo > 0.2f ? 2 : (mo > 0.1f ? 1 : 0);
        g_state[gid] = st;
    }

    // local CCL in shared memory
    const unsigned lid = tid;
    ls[lid] = st;
    lp[lid] = lid;
    sflag[lid] = 0;
    __syncthreads();

    if (st) {
        if (lx > 0            && ls[lid - 1])  lunion(lp, lid, lid - 1);
        if (ly > 0) {
            if (lx > 0        && ls[lid - 33]) lunion(lp, lid, lid - 33);
            if (ls[lid - 32])                  lunion(lp, lid, lid - 32);
            if (lx < 31       && ls[lid - 31]) lunion(lp, lid, lid - 31);
        }
    }
    __syncthreads();

    unsigned r = 0;
    if (st) {
        r = lfind(lp, lid);
        if (st == 2) sflag[r] = 1;  // only 1s written: benign race
    }
    __syncthreads();

    if (st) {
        unsigned rg = b * IMG + (tileY + (r >> 5)) * W + tileX + (r & 31);
        g_parent[gid] = rg;
        if (r == lid) {
            g_flag[gid] = sflag[lid];
            unsigned slot = atomicAdd(&scnt, 1u);
            slist[slot] = (unsigned short)lid;
        }
    }
    __syncthreads();

    if (tid == 0) sbase = atomicAdd(&g_nroots, scnt);
    __syncthreads();
    if (tid < scnt) {
        unsigned l = slist[tid];
        g_roots[sbase + tid] = b * IMG + (tileY + (l >> 5)) * W + tileX + (l & 31);
    }
}

// ================= cross-tile border unions =================
#define VB_PER 31744u              // 31 seams * 1024
#define VB_TOT (4u * VB_PER)

__global__ void k_merge_border() {
    unsigned id = blockIdx.x * blockDim.x + threadIdx.x;
    bool vert = id < VB_TOT;
    unsigned t = vert ? id : id - VB_TOT;
    unsigned b = t / VB_PER;
    unsigned r = t % VB_PER;

    if (vert) {
        unsigned c = r >> 10;
        unsigned y = r & 1023;
        unsigned x = (c + 1) << 5;
        unsigned i = b * IMG + y * W + x;
        if (!g_state[i]) return;
        unsigned pi = g_parent[i];
        unsigned j = i - 1;
        if (y > 0     && g_state[j - W]) gunion(pi, g_parent[j - W]);
        if (g_state[j])                  gunion(pi, g_parent[j]);
        if (y < H - 1 && g_state[j + W]) gunion(pi, g_parent[j + W]);
    } else {
        unsigned rr = r >> 10;
        unsigned x = r & 1023;
        unsigned y = (rr + 1) << 5;
        unsigned i = b * IMG + y * W + x;
        if (!g_state[i]) return;
        unsigned pi = g_parent[i];
        unsigned j = i - W;
        if (x > 0     && g_state[j - 1]) gunion(pi, g_parent[j - 1]);
        if (g_state[j])                  gunion(pi, g_parent[j]);
        if (x < W - 1 && g_state[j + 1]) gunion(pi, g_parent[j + 1]);
    }
}

// ================= flatten roots + propagate strong flag =================
__global__ void k_flatten() {
    unsigned n = g_nroots;
    for (unsigned j = blockIdx.x * blockDim.x + threadIdx.x; j < n;
         j += gridDim.x * blockDim.x) {
        unsigned i = g_roots[j];
        unsigned rt = gfind(i);
        g_parent[i] = rt;
        if (g_flag[i]) g_flag[rt] = 1;   // OR-style, only 1s written
    }
}

// ================= final edge output =================
__global__ __launch_bounds__(1024) void k_final(float* __restrict__ edgeOut) {
    int gx = blockIdx.x * 32 + threadIdx.x;
    int gy = blockIdx.y * 32 + threadIdx.y;
    unsigned i = blockIdx.z * IMG + gy * W + gx;
    float v = 0.f;
    if (g_state[i]) {
        unsigned p  = __ldcg(&g_parent[i]);       // local root (same tile)
        unsigned rt = __ldcg(&g_parent[p]);       // global root
        if (g_flag[rt]) v = 1.f;
    }
    edgeOut[i] = v;
}

// ---------------- launch ----------------
extern "C" void kernel_launch(void* const* d_in, const int* in_sizes, int n_in,
                              void* d_out, int out_size) {
    const float* x = (const float*)d_in[0];
    float* magOut  = (float*)d_out;
    float* edgeOut = magOut + (size_t)NPIX;

    k_reset<<<1, 1>>>();

    dim3 fblk(TX, TY, 1);
    dim3 fgrd(W / TX, H / TY, BATCH);
    k_fused<<<fgrd, fblk>>>(x, magOut);

    unsigned nborder = 2u * VB_TOT;
    k_merge_border<<<(nborder + 255) / 256, 256>>>();

    k_flatten<<<1024, 256>>>();

    dim3 eblk(32, 32, 1);
    dim3 egrd(W / 32, H / 32, BATCH);
    k_final<<<egrd, eblk>>>(edgeOut);
}

// round 5
// speedup vs baseline: 2.0007x; 1.0097x over previous
#include <cuda_runtime.h>

#define BATCH 4
#define H 1024
#define W 1024
#define IMG (H * W)
#define NPIX (BATCH * IMG)
#define NTILES (BATCH * 32 * 32)   // 32x32 tiles of 32x32 px
#define MAXROOTS 512               // theory max 256 (8-conn), 2x margin

// ---------------- scratch ----------------
__device__ unsigned short g_pack[NPIX];     // bits[14:16)=state, bits[0:10)=local root idx
__device__ unsigned int   g_parent[NPIX];   // valid ONLY at local-root positions
__device__ unsigned char  g_flag[NPIX];     // valid ONLY at local-root positions
__device__ unsigned short g_roots[NTILES * MAXROOTS];
__device__ unsigned int   g_cnt[NTILES];

__constant__ int c_dy[8] = { 0, 1, 1, 1, 0, -1, -1, -1 };
__constant__ int c_dx[8] = { 1, 1, 0, -1, -1, -1, 0, 1 };

#define GW0 0.40261994f
#define GW1 0.24420134f
#define GW2 0.05448868f
#define TAN22 0.41421356237309503f
#define TAN67 2.4142135623730951f

__device__ __forceinline__ int reflect_idx(int i, int n) {
    if (i < 0) return -i;
    if (i >= n) return 2 * n - 2 - i;
    return i;
}

// ---- shared-memory union-find ----
__device__ __forceinline__ unsigned lfind(unsigned* p, unsigned i) {
    volatile unsigned* vp = (volatile unsigned*)p;
    unsigned q = vp[i];
    while (q != i) {
        unsigned qq = vp[q];
        if (qq != q) vp[i] = qq;
        i = q; q = qq;
    }
    return i;
}
__device__ __forceinline__ void lunion(unsigned* p, unsigned a, unsigned b) {
    while (true) {
        a = lfind(p, a);
        b = lfind(p, b);
        if (a == b) return;
        unsigned lo = min(a, b), hi = max(a, b);
        unsigned old = atomicCAS(&p[hi], hi, lo);
        if (old == hi) return;
        a = lo; b = old;
    }
}

// ---- global union-find (root positions only) ----
__device__ __forceinline__ unsigned gfind(unsigned i) {
    unsigned p = __ldcg(&g_parent[i]);
    while (p != i) {
        unsigned gp = __ldcg(&g_parent[p]);
        if (gp != p) __stcg(&g_parent[i], gp);
        i = p; p = gp;
    }
    return i;
}
__device__ __forceinline__ void gunion(unsigned a, unsigned b) {
    while (true) {
        a = gfind(a);
        b = gfind(b);
        if (a == b) return;
        unsigned lo = min(a, b), hi = max(a, b);
        unsigned old = atomicCAS(&g_parent[hi], hi, lo);
        if (old == hi) return;
        a = lo; b = old;
    }
}

// decode a pixel's local-root global position from its packed value
__device__ __forceinline__ unsigned rootPos(unsigned j, unsigned pk) {
    unsigned l = pk & 1023u;
    unsigned b = j >> 20;
    unsigned y = (j >> 10) & 1023u;
    unsigned x = j & 1023u;
    return (b << 20) + (((y & ~31u) + (l >> 5)) << 10) + (x & ~31u) + (l & 31u);
}

// ================= fused stencil + NMS + threshold + local CCL =================
#define TX 32
#define TY 32

__global__ __launch_bounds__(1024) void k_fused(const float* __restrict__ x,
                                                float* __restrict__ magOut) {
    __shared__ float sG[40][41];
    __shared__ float sH[40][37];
    __shared__ float sV[36][37];
    __shared__ float sM[34][35];
    __shared__ unsigned char sD[34][35];
    __shared__ unsigned      lp[1024];
    __shared__ unsigned char ls[1024];
    __shared__ unsigned char sflag[1024];
    __shared__ unsigned scnt;

    const int tileX = blockIdx.x * TX;
    const int tileY = blockIdx.y * TY;
    const int b     = blockIdx.z;
    const int tid   = threadIdx.y * TX + threadIdx.x;
    const unsigned tileId = ((unsigned)b * 32 + blockIdx.y) * 32 + blockIdx.x;
    const float* base = x + (size_t)b * 3 * IMG;

    if (tid == 0) scnt = 0;

    for (int idx = tid; idx < 40 * 40; idx += 1024) {
        int r = idx / 40, c = idx % 40;
        int yy = reflect_idx(tileY - 4 + r, H);
        int xx = reflect_idx(tileX - 4 + c, W);
        int o = yy * W + xx;
        sG[r][c] = 0.299f * base[o] + 0.587f * base[IMG + o] + 0.114f * base[2 * IMG + o];
    }
    __syncthreads();

    for (int idx = tid; idx < 40 * 36; idx += 1024) {
        int r = idx / 36, c = idx % 36;
        int gx = tileX - 2 + c;
        float s = 0.f;
        const float w[5] = { GW2, GW1, GW0, GW1, GW2 };
#pragma unroll
        for (int k = 0; k < 5; k++) {
            int lx = reflect_idx(gx + k - 2, W) - (tileX - 4);
            s += w[k] * sG[r][lx];
        }
        sH[r][c] = s;
    }
    __syncthreads();

    for (int idx = tid; idx < 36 * 36; idx += 1024) {
        int r = idx / 36, c = idx % 36;
        int gy = tileY - 2 + r;
        float s = 0.f;
        const float w[5] = { GW2, GW1, GW0, GW1, GW2 };
#pragma unroll
        for (int k = 0; k < 5; k++) {
            int ly = reflect_idx(gy + k - 2, H) - (tileY - 4);
            s += w[k] * sH[ly][c];
        }
        sV[r][c] = s;
    }
    __syncthreads();

    for (int idx = tid; idx < 34 * 34; idx += 1024) {
        int r = idx / 34, c = idx % 34;
        int gy = tileY - 1 + r;
        int gx = tileX - 1 + c;
        int xm = max(gx - 1, 0), xp = min(gx + 1, W - 1);
        int ym = max(gy - 1, 0), yp = min(gy + 1, H - 1);
        int xc = min(max(gx, 0), W - 1), yc = min(max(gy, 0), H - 1);
        int lxm = xm - (tileX - 2), lxp = xp - (tileX - 2), lxc = xc - (tileX - 2);
        int lym = ym - (tileY - 2), lyp = yp - (tileY - 2), lyc = yc - (tileY - 2);

        float a00 = sV[lym][lxm], a01 = sV[lym][lxc], a02 = sV[lym][lxp];
        float a10 = sV[lyc][lxm],                     a12 = sV[lyc][lxp];
        float a20 = sV[lyp][lxm], a21 = sV[lyp][lxc], a22 = sV[lyp][lxp];

        float gxv = (a02 - a00) + 2.f * (a12 - a10) + (a22 - a20);
        float gyv = (a20 - a00) + 2.f * (a21 - a01) + (a22 - a02);

        float mag = sqrtf(gxv * gxv + gyv * gyv + 1e-6f);

        float ax = fabsf(gxv), ay = fabsf(gyv);
        int d;
        if (ay <= TAN22 * ax)      d = (gxv >= 0.f) ? 0 : 4;
        else if (ay >= TAN67 * ax) d = (gyv >= 0.f) ? 2 : 6;
        else {
            if (gxv > 0.f) d = (gyv > 0.f) ? 1 : 7;
            else           d = (gyv > 0.f) ? 3 : 5;
        }
        sM[r][c] = mag;
        sD[r][c] = (unsigned char)d;
    }
    __syncthreads();

    const int lx = threadIdx.x, ly = threadIdx.y;
    const int gx = tileX + lx, gy = tileY + ly;
    const unsigned gid = b * IMG + gy * W + gx;
    unsigned char st;
    {
        float m = sM[ly + 1][lx + 1];
        int d  = sD[ly + 1][lx + 1];
        int dn = (d + 4) & 7;

        int y1 = gy + c_dy[d],  x1 = gx + c_dx[d];
        int y2 = gy + c_dy[dn], x2 = gx + c_dx[dn];
        float n1 = (y1 >= 0 && y1 < H && x1 >= 0 && x1 < W)
                   ? sM[ly + 1 + c_dy[d]][lx + 1 + c_dx[d]] : 0.f;
        float n2 = (y2 >= 0 && y2 < H && x2 >= 0 && x2 < W)
                   ? sM[ly + 1 + c_dy[dn]][lx + 1 + c_dx[dn]] : 0.f;

        bool keep = (m > n1) && (m > n2);
        float mo = keep ? m : 0.f;
        magOut[gid] = mo;
        st = mo > 0.2f ? 2 : (mo > 0.1f ? 1 : 0);
    }

    // local CCL
    const unsigned lid = tid;
    ls[lid] = st;
    lp[lid] = lid;
    sflag[lid] = 0;
    __syncthreads();

    if (st) {
        if (lx > 0            && ls[lid - 1])  lunion(lp, lid, lid - 1);
        if (ly > 0) {
            if (lx > 0        && ls[lid - 33]) lunion(lp, lid, lid - 33);
            if (ls[lid - 32])                  lunion(lp, lid, lid - 32);
            if (lx < 31       && ls[lid - 31]) lunion(lp, lid, lid - 31);
        }
    }
    __syncthreads();

    unsigned r = 0;
    if (st) {
        r = lfind(lp, lid);
        if (st == 2) sflag[r] = 1;   // only 1s written: benign race
    }
    __syncthreads();

    g_pack[gid] = st ? (unsigned short)(((unsigned)st << 14) | r) : 0;
    if (st && r == lid) {
        g_parent[gid] = gid;
        g_flag[gid]   = sflag[lid];
        unsigned slot = atomicAdd(&scnt, 1u);
        if (slot < MAXROOTS) g_roots[tileId * MAXROOTS + slot] = (unsigned short)lid;
    }
    __syncthreads();
    if (tid == 0) g_cnt[tileId] = min(scnt, (unsigned)MAXROOTS);
}

// ================= cross-tile border unions =================
#define VB_PER 31744u              // 31 seams * 1024
#define VB_TOT (4u * VB_PER)

__global__ void k_merge_border() {
    unsigned id = blockIdx.x * blockDim.x + threadIdx.x;
    bool vert = id < VB_TOT;
    unsigned t = vert ? id : id - VB_TOT;
    unsigned b = t / VB_PER;
    unsigned r = t % VB_PER;

    unsigned i, j, s1, s2, s3;
    if (vert) {
        unsigned c = r >> 10;
        unsigned y = r & 1023;
        unsigned x = (c + 1) << 5;
        i = b * IMG + y * W + x;
        j = i - 1;
        s1 = (y > 0)     ? j - W : 0xFFFFFFFFu;
        s2 = j;
        s3 = (y < H - 1) ? j + W : 0xFFFFFFFFu;
    } else {
        unsigned rr = r >> 10;
        unsigned x = r & 1023;
        unsigned y = (rr + 1) << 5;
        i = b * IMG + y * W + x;
        j = i - W;
        s1 = (x > 0)     ? j - 1 : 0xFFFFFFFFu;
        s2 = j;
        s3 = (x < W - 1) ? j + 1 : 0xFFFFFFFFu;
    }

    unsigned pki = g_pack[i];
    if (!(pki >> 14)) return;
    unsigned ri = rootPos(i, pki);

    if (s1 != 0xFFFFFFFFu) { unsigned pk = g_pack[s1]; if (pk >> 14) gunion(ri, rootPos(s1, pk)); }
    { unsigned pk = g_pack[s2]; if (pk >> 14) gunion(ri, rootPos(s2, pk)); }
    if (s3 != 0xFFFFFFFFu) { unsigned pk = g_pack[s3]; if (pk >> 14) gunion(ri, rootPos(s3, pk)); }
}

// ================= flatten roots + OR strong flag to global root =================
__global__ void k_flatten() {
    unsigned tile = blockIdx.x;
    unsigned cnt  = g_cnt[tile];
    unsigned b    = tile >> 10;
    unsigned by   = (tile >> 5) & 31u;
    unsigned bx   = tile & 31u;
    unsigned base = (b << 20) + ((by << 5) << 10) + (bx << 5);
    for (unsigned s = threadIdx.x; s < cnt; s += blockDim.x) {
        unsigned l = g_roots[tile * MAXROOTS + s];
        unsigned pos = base + ((l >> 5) << 10) + (l & 31u);
        unsigned rt = gfind(pos);
        g_parent[pos] = rt;
        if (rt != pos && g_flag[pos]) g_flag[rt] = 1;
    }
}

// ================= push resolved flag down to local roots =================
__global__ void k_flatten2() {
    unsigned tile = blockIdx.x;
    unsigned cnt  = g_cnt[tile];
    unsigned b    = tile >> 10;
    unsigned by   = (tile >> 5) & 31u;
    unsigned bx   = tile & 31u;
    unsigned base = (b << 20) + ((by << 5) << 10) + (bx << 5);
    for (unsigned s = threadIdx.x; s < cnt; s += blockDim.x) {
        unsigned l = g_roots[tile * MAXROOTS + s];
        unsigned pos = base + ((l >> 5) << 10) + (l & 31u);
        unsigned rt = __ldcg(&g_parent[pos]);
        if (rt != pos) g_flag[pos] = g_flag[rt];
    }
}

// ================= final edge output (loop-free, tile-local flag lookup) =====
__global__ __launch_bounds__(1024) void k_final(float* __restrict__ edgeOut) {
    unsigned gx = blockIdx.x * 32 + threadIdx.x;
    unsigned gy = blockIdx.y * 32 + threadIdx.y;
    unsigned i  = ((unsigned)blockIdx.z << 20) + (gy << 10) + gx;
    unsigned pk = g_pack[i];
    float v = 0.f;
    if (pk >> 14) {
        unsigned l = pk & 1023u;
        unsigned pos = ((unsigned)blockIdx.z << 20)
                     + (((blockIdx.y << 5) + (l >> 5)) << 10)
                     + (blockIdx.x << 5) + (l & 31u);
        v = g_flag[pos] ? 1.f : 0.f;
    }
    edgeOut[i] = v;
}

// ---------------- launch ----------------
extern "C" void kernel_launch(void* const* d_in, const int* in_sizes, int n_in,
                              void* d_out, int out_size) {
    const float* x = (const float*)d_in[0];
    float* magOut  = (float*)d_out;
    float* edgeOut = magOut + (size_t)NPIX;

    dim3 fblk(TX, TY, 1);
    dim3 fgrd(W / TX, H / TY, BATCH);
    k_fused<<<fgrd, fblk>>>(x, magOut);

    unsigned nborder = 2u * VB_TOT;
    k_merge_border<<<(nborder + 255) / 256, 256>>>();

    k_flatten<<<NTILES, 128>>>();
    k_flatten2<<<NTILES, 128>>>();

    dim3 eblk(32, 32, 1);
    dim3 egrd(W / 32, H / 32, BATCH);
    k_final<<<egrd, eblk>>>(edgeOut);
}

// round 7
// speedup vs baseline: 2.3923x; 1.1957x over previous
#include <cuda_runtime.h>

#define BATCH 4
#define H 1024
#define W 1024
#define IMG (H * W)
#define NPIX (BATCH * IMG)
#define NTILES (BATCH * 32 * 32)
#define MAXROOTS 512

// ---------------- scratch ----------------
__device__ unsigned short g_pack[NPIX];   // bits[14:16)=state, bits[0:10)=local root idx
__device__ unsigned int   g_parent[NPIX]; // valid ONLY at local-root positions
__device__ unsigned char  g_flag[NPIX];   // valid ONLY at root positions
__device__ unsigned short g_roots[NTILES * MAXROOTS];
__device__ unsigned int   g_cnt[NTILES];

__constant__ int c_dy[8] = { 0, 1, 1, 1, 0, -1, -1, -1 };
__constant__ int c_dx[8] = { 1, 1, 0, -1, -1, -1, 0, 1 };

#define GW0 0.40261994f
#define GW1 0.24420134f
#define GW2 0.05448868f
#define TAN22 0.41421356237309503f
#define TAN67 2.4142135623730951f

__device__ __forceinline__ int reflect_idx(int i, int n) {
    if (i < 0) return -i;
    if (i >= n) return 2 * n - 2 - i;
    return i;
}

// ---- shared-memory union-find ----
__device__ __forceinline__ unsigned lfind(unsigned* p, unsigned i) {
    volatile unsigned* vp = (volatile unsigned*)p;
    unsigned q = vp[i];
    while (q != i) {
        unsigned qq = vp[q];
        if (qq != q) vp[i] = qq;
        i = q; q = qq;
    }
    return i;
}
__device__ __forceinline__ void lunion(unsigned* p, unsigned a, unsigned b) {
    while (true) {
        a = lfind(p, a);
        b = lfind(p, b);
        if (a == b) return;
        unsigned lo = min(a, b), hi = max(a, b);
        unsigned old = atomicCAS(&p[hi], hi, lo);
        if (old == hi) return;
        a = lo; b = old;
    }
}

// ---- global union-find (root positions only) ----
__device__ __forceinline__ unsigned gfind(unsigned i) {
    unsigned p = __ldcg(&g_parent[i]);
    while (p != i) {
        unsigned gp = __ldcg(&g_parent[p]);
        if (gp != p) __stcg(&g_parent[i], gp);
        i = p; p = gp;
    }
    return i;
}
__device__ __forceinline__ void gunion(unsigned a, unsigned b) {
    while (true) {
        a = gfind(a);
        b = gfind(b);
        if (a == b) return;
        unsigned lo = min(a, b), hi = max(a, b);
        unsigned old = atomicCAS(&g_parent[hi], hi, lo);
        if (old == hi) return;
        a = lo; b = old;
    }
}

// decode a pixel's local-root global position from its packed value
__device__ __forceinline__ unsigned rootPos(unsigned j, unsigned pk) {
    unsigned l = pk & 1023u;
    unsigned b = j >> 20;
    unsigned y = (j >> 10) & 1023u;
    unsigned x = j & 1023u;
    return (b << 20) + (((y & ~31u) + (l >> 5)) << 10) + (x & ~31u) + (l & 31u);
}

// ================= fused stencil + NMS + threshold + local CCL =================
#define TX 32
#define TY 32

__global__ __launch_bounds__(1024) void k_fused(const float* __restrict__ x,
                                                float* __restrict__ magOut) {
    __shared__ float sG[40][41];
    __shared__ float sH[40][37];
    __shared__ float sV[36][37];
    __shared__ float sM[34][35];
    __shared__ unsigned char sD[34][35];
    __shared__ unsigned      lp[1024];
    __shared__ unsigned char ls[1024];
    __shared__ unsigned char sflag[1024];
    __shared__ unsigned scnt;

    const int tileX = blockIdx.x * TX;
    const int tileY = blockIdx.y * TY;
    const int b     = blockIdx.z;
    const int tid   = threadIdx.y * TX + threadIdx.x;
    const unsigned tileId = ((unsigned)b * 32 + blockIdx.y) * 32 + blockIdx.x;
    const float* base = x + (size_t)b * 3 * IMG;

    if (tid == 0) scnt = 0;

    for (int idx = tid; idx < 40 * 40; idx += 1024) {
        int r = idx / 40, c = idx % 40;
        int yy = reflect_idx(tileY - 4 + r, H);
        int xx = reflect_idx(tileX - 4 + c, W);
        int o = yy * W + xx;
        sG[r][c] = 0.299f * base[o] + 0.587f * base[IMG + o] + 0.114f * base[2 * IMG + o];
    }
    __syncthreads();

    for (int idx = tid; idx < 40 * 36; idx += 1024) {
        int r = idx / 36, c = idx % 36;
        int gx = tileX - 2 + c;
        float s = 0.f;
        const float w[5] = { GW2, GW1, GW0, GW1, GW2 };
#pragma unroll
        for (int k = 0; k < 5; k++) {
            int lx = reflect_idx(gx + k - 2, W) - (tileX - 4);
            s += w[k] * sG[r][lx];
        }
        sH[r][c] = s;
    }
    __syncthreads();

    for (int idx = tid; idx < 36 * 36; idx += 1024) {
        int r = idx / 36, c = idx % 36;
        int gy = tileY - 2 + r;
        float s = 0.f;
        const float w[5] = { GW2, GW1, GW0, GW1, GW2 };
#pragma unroll
        for (int k = 0; k < 5; k++) {
            int ly = reflect_idx(gy + k - 2, H) - (tileY - 4);
            s += w[k] * sH[ly][c];
        }
        sV[r][c] = s;
    }
    __syncthreads();

    for (int idx = tid; idx < 34 * 34; idx += 1024) {
        int r = idx / 34, c = idx % 34;
        int gy = tileY - 1 + r;
        int gx = tileX - 1 + c;
        int xm = max(gx - 1, 0), xp = min(gx + 1, W - 1);
        int ym = max(gy - 1, 0), yp = min(gy + 1, H - 1);
        int xc = min(max(gx, 0), W - 1), yc = min(max(gy, 0), H - 1);
        int lxm = xm - (tileX - 2), lxp = xp - (tileX - 2), lxc = xc - (tileX - 2);
        int lym = ym - (tileY - 2), lyp = yp - (tileY - 2), lyc = yc - (tileY - 2);

        float a00 = sV[lym][lxm], a01 = sV[lym][lxc], a02 = sV[lym][lxp];
        float a10 = sV[lyc][lxm],                     a12 = sV[lyc][lxp];
        float a20 = sV[lyp][lxm], a21 = sV[lyp][lxc], a22 = sV[lyp][lxp];

        float gxv = (a02 - a00) + 2.f * (a12 - a10) + (a22 - a20);
        float gyv = (a20 - a00) + 2.f * (a21 - a01) + (a22 - a02);

        float mag = sqrtf(gxv * gxv + gyv * gyv + 1e-6f);

        float ax = fabsf(gxv), ay = fabsf(gyv);
        int d;
        if (ay <= TAN22 * ax)      d = (gxv >= 0.f) ? 0 : 4;
        else if (ay >= TAN67 * ax) d = (gyv >= 0.f) ? 2 : 6;
        else {
            if (gxv > 0.f) d = (gyv > 0.f) ? 1 : 7;
            else           d = (gyv > 0.f) ? 3 : 5;
        }
        sM[r][c] = mag;
        sD[r][c] = (unsigned char)d;
    }
    __syncthreads();

    const int lx = threadIdx.x, ly = threadIdx.y;
    const int gx = tileX + lx, gy = tileY + ly;
    const unsigned gid = b * IMG + gy * W + gx;
    unsigned char st;
    {
        float m = sM[ly + 1][lx + 1];
        int d  = sD[ly + 1][lx + 1];
        int dn = (d + 4) & 7;

        int y1 = gy + c_dy[d],  x1 = gx + c_dx[d];
        int y2 = gy + c_dy[dn], x2 = gx + c_dx[dn];
        float n1 = (y1 >= 0 && y1 < H && x1 >= 0 && x1 < W)
                   ? sM[ly + 1 + c_dy[d]][lx + 1 + c_dx[d]] : 0.f;
        float n2 = (y2 >= 0 && y2 < H && x2 >= 0 && x2 < W)
                   ? sM[ly + 1 + c_dy[dn]][lx + 1 + c_dx[dn]] : 0.f;

        bool keep = (m > n1) && (m > n2);
        float mo = keep ? m : 0.f;
        magOut[gid] = mo;
        st = mo > 0.2f ? 2 : (mo > 0.1f ? 1 : 0);
    }

    // local CCL with reduced unions (Playne-Hawick style)
    const unsigned lid = tid;
    ls[lid] = st;
    lp[lid] = lid;
    sflag[lid] = 0;
    __syncthreads();

    if (st) {
        bool up = (ly > 0) && ls[lid - 32];
        bool ul = (ly > 0) && (lx > 0)  && ls[lid - 33];
        bool ur = (ly > 0) && (lx < 31) && ls[lid - 31];
        bool lf = (lx > 0) && ls[lid - 1];
        if (up) lunion(lp, lid, lid - 32);
        else {
            if (ul) lunion(lp, lid, lid - 33);
            if (ur) lunion(lp, lid, lid - 31);
        }
        if (lf && !(up && ul)) lunion(lp, lid, lid - 1);
    }
    __syncthreads();

    unsigned r = 0;
    if (st) {
        r = lfind(lp, lid);
        if (st == 2) sflag[r] = 1;   // only 1s written: benign race
    }
    __syncthreads();

    g_pack[gid] = st ? (unsigned short)(((unsigned)st << 14) | r) : 0;
    if (st && r == lid) {
        g_parent[gid] = gid;
        g_flag[gid]   = sflag[lid];
        unsigned slot = atomicAdd(&scnt, 1u);
        if (slot < MAXROOTS) g_roots[tileId * MAXROOTS + slot] = (unsigned short)lid;
    }
    __syncthreads();
    if (tid == 0) g_cnt[tileId] = min(scnt, (unsigned)MAXROOTS);
}

// ================= cross-tile border unions (well-founded reduction) ==========
#define VB_PER 31744u              // 31 seams * 1024
#define VB_TOT (4u * VB_PER)

__global__ void k_merge_border() {
    unsigned id = blockIdx.x * blockDim.x + threadIdx.x;
    bool vert = id < VB_TOT;
    unsigned t = vert ? id : id - VB_TOT;
    unsigned b = t / VB_PER;
    unsigned r = t % VB_PER;

    if (vert) {
        // p=(x,y), x multiple of 32; neighbors in left tile at x-1.
        // Induction on y (base y%32==0 handled via horizontal kernel's no-skip corner).
        unsigned c = r >> 10;
        unsigned y = r & 1023;
        unsigned x = (c + 1) << 5;
        unsigned i = b * IMG + y * W + x;
        unsigned pki = g_pack[i];
        if (!(pki >> 14)) return;
        unsigned ri = rootPos(i, pki);

        unsigned pkL = g_pack[i - 1];
        bool bL = (pkL >> 14) != 0;
        unsigned pkP = 0, pkUL = 0;
        bool bP = false, bUL = false;
        if (y > 0) {
            pkP  = g_pack[i - W];     bP  = (pkP  >> 14) != 0;
            pkUL = g_pack[i - W - 1]; bUL = (pkUL >> 14) != 0;
        }
        // p~P guaranteed when bP: intra-tile (y%32!=0, local CCL) or corner
        // (y%32==0: horizontal kernel unions p~U directly, no skip at x%32==0).
        bool pP = bP;
        if (bL) {
            if (!(pP && bUL)) gunion(ri, rootPos(i - 1, pkL));
        } else {
            if (bUL && !pP) gunion(ri, rootPos(i - W - 1, pkUL));
            if (y < H - 1) {
                unsigned pkDL = g_pack[i + W - 1];
                if (pkDL >> 14) gunion(ri, rootPos(i + W - 1, pkDL));
            }
        }
    } else {
        // p=(x,y), y multiple of 32; neighbors in upper tile at y-1.
        // Skips allowed only when x%32 != 0 (p~L is intra-tile); corners do full work.
        unsigned rr = r >> 10;
        unsigned x = r & 1023;
        unsigned y = (rr + 1) << 5;
        unsigned i = b * IMG + y * W + x;
        unsigned pki = g_pack[i];
        if (!(pki >> 14)) return;
        unsigned ri = rootPos(i, pki);

        unsigned pkU = g_pack[i - W];
        bool bU = (pkU >> 14) != 0;
        bool intra = (x & 31u) != 0;
        unsigned pkL = 0, pkUL = 0;
        bool bL = false, bUL = false;
        if (x > 0) {
            pkL  = g_pack[i - 1];     bL  = (pkL  >> 14) != 0;
            pkUL = g_pack[i - W - 1]; bUL = (pkUL >> 14) != 0;
        }
        bool skip = intra && bL && bUL;   // p~L (local), L~UL (horiz @ x-1, induction)
        if (bU) {
            if (!skip) gunion(ri, rootPos(i - W, pkU));
        } else {
            if (bUL && !(intra && bL)) gunion(ri, rootPos(i - W - 1, pkUL));
            if (x < W - 1) {
                unsigned pkUR = g_pack[i - W + 1];
                if (pkUR >> 14) gunion(ri, rootPos(i - W + 1, pkUR));
            }
        }
    }
}

// ================= flatten roots + OR strong flag to global root =================
__global__ void k_flatten() {
    unsigned tile = blockIdx.x;
    unsigned cnt  = g_cnt[tile];
    unsigned b    = tile >> 10;
    unsigned by   = (tile >> 5) & 31u;
    unsigned bx   = tile & 31u;
    unsigned base = (b << 20) + ((by << 5) << 10) + (bx << 5);
    for (unsigned s = threadIdx.x; s < cnt; s += blockDim.x) {
        unsigned l = g_roots[tile * MAXROOTS + s];
        unsigned pos = base + ((l >> 5) << 10) + (l & 31u);
        unsigned rt = gfind(pos);
        g_parent[pos] = rt;
        if (rt != pos && g_flag[pos]) g_flag[rt] = 1;
    }
}

// ================= final edge output (loop to true root: race-robust) ========
__global__ __launch_bounds__(1024) void k_final(float* __restrict__ edgeOut) {
    unsigned gx = blockIdx.x * 32 + threadIdx.x;
    unsigned gy = blockIdx.y * 32 + threadIdx.y;
    unsigned i  = ((unsigned)blockIdx.z << 20) + (gy << 10) + gx;
    unsigned pk = g_pack[i];
    float v = 0.f;
    if (pk >> 14) {
        unsigned l = pk & 1023u;
        unsigned pos = ((unsigned)blockIdx.z << 20)
                     + (((blockIdx.y << 5) + (l >> 5)) << 10)
                     + (blockIdx.x << 5) + (l & 31u);
        unsigned rt = __ldcg(&g_parent[pos]);
        unsigned p  = __ldcg(&g_parent[rt]);
        while (p != rt) { rt = p; p = __ldcg(&g_parent[rt]); }  // usually 0 iters
        v = g_flag[rt] ? 1.f : 0.f;
    }
    edgeOut[i] = v;
}

// ---------------- launch ----------------
extern "C" void kernel_launch(void* const* d_in, const int* in_sizes, int n_in,
                              void* d_out, int out_size) {
    const float* x = (const float*)d_in[0];
    float* magOut  = (float*)d_out;
    float* edgeOut = magOut + (size_t)NPIX;

    dim3 fblk(TX, TY, 1);
    dim3 fgrd(W / TX, H / TY, BATCH);
    k_fused<<<fgrd, fblk>>>(x, magOut);

    unsigned nborder = 2u * VB_TOT;
    k_merge_border<<<(nborder + 255) / 256, 256>>>();

    k_flatten<<<NTILES, 128>>>();

    dim3 eblk(32, 32, 1);
    dim3 egrd(W / 32, H / 32, BATCH);
    k_final<<<egrd, eblk>>>(edgeOut);
}